// round 1
// baseline (speedup 1.0000x reference)
#include <cuda_runtime.h>
#include <math.h>

#define Bx   4
#define Tx   12
#define Nx   3000
#define Hx   64
#define Mx   32
#define Ex   96000
#define GMMx 96
#define RINx 161
#define GINx 225
#define D3x  675
#define BNx  (Bx*Nx)

// ---------------- device scratch (static, allowed) ----------------
__device__ int   g_cnt[Nx];
__device__ int   g_cur[Nx];
__device__ int   g_off[Nx + 1];
__device__ int   g_eid[Ex];
__device__ int   g_srcs[Ex];
__device__ float g_ws[Ex];

__device__ float g_h   [BNx * Hx];
__device__ float g_xs1 [BNx * GMMx];
__device__ float g_z   [BNx * Hx];
__device__ float g_az  [BNx * Hx];
__device__ float g_repr[BNx * 2 * Hx];
__device__ float g_x2  [BNx * RINx];
__device__ float g_rh  [BNx * Hx];
__device__ float g_gg  [BNx * Hx];
__device__ float g_a1  [BNx * GINx];
__device__ float g_a2  [BNx * GINx];

// ---------------- preprocessing: CSR by dst, deterministic ----------------
__global__ void k_init() {
    int i = blockIdx.x * blockDim.x + threadIdx.x;
    if (i < Nx) { g_cnt[i] = 0; g_cur[i] = 0; }
    if (i < BNx * Hx) g_h[i] = 0.f;
}

__global__ void k_count(const int* __restrict__ ei) {
    int e = blockIdx.x * blockDim.x + threadIdx.x;
    if (e < Ex) atomicAdd(&g_cnt[ei[Ex + e]], 1);
}

__global__ void k_scan() {   // 1 warp
    int lane = threadIdx.x;
    const int CH = (Nx + 31) / 32;
    int st = lane * CH, en = min(Nx, st + CH);
    int s = 0;
    for (int i = st; i < en; i++) s += g_cnt[i];
    int acc = s;
    for (int o = 1; o < 32; o <<= 1) {
        int v = __shfl_up_sync(0xffffffffu, acc, o);
        if (lane >= o) acc += v;
    }
    int base = acc - s;
    for (int i = st; i < en; i++) { g_off[i] = base; base += g_cnt[i]; }
    if (lane == 31) g_off[Nx] = base;
}

__global__ void k_scatter(const int* __restrict__ ei) {
    int e = blockIdx.x * blockDim.x + threadIdx.x;
    if (e < Ex) {
        int d = ei[Ex + e];
        int p = atomicAdd(&g_cur[d], 1);
        g_eid[g_off[d] + p] = e;
    }
}

__global__ void k_sortfill(const int* __restrict__ ei, const float* __restrict__ ew) {
    int d = blockIdx.x * blockDim.x + threadIdx.x;
    if (d >= Nx) return;
    int s = g_off[d], t = g_off[d + 1];
    for (int i = s + 1; i < t; i++) {        // insertion sort by edge id -> deterministic
        int v = g_eid[i];
        int j = i - 1;
        while (j >= s && g_eid[j] > v) { g_eid[j + 1] = g_eid[j]; j--; }
        g_eid[j + 1] = v;
    }
    for (int i = s; i < t; i++) {
        int e = g_eid[i];
        g_srcs[i] = ei[e];
        g_ws[i]   = ew[e];
    }
}

// ---------------- step kernels ----------------
// raw = h @ W_gmm + b; mu | softplus | softmax  -> g_xs1, predictions slice
__global__ void k_gmm(const float* __restrict__ Wg, const float* __restrict__ bg,
                      float* __restrict__ pred_out, int t) {
    int row = blockIdx.x;            // b*N + n
    int tid = threadIdx.x;           // 0..95
    __shared__ float sh[Hx];
    if (tid < Hx) sh[tid] = g_h[(size_t)row * Hx + tid];
    __syncthreads();
    float acc = bg[tid];
    #pragma unroll
    for (int k = 0; k < Hx; k++) acc = fmaf(sh[k], Wg[k * GMMx + tid], acc);
    float val;
    if (tid < Mx) {
        val = acc;                                   // mu
    } else if (tid < 2 * Mx) {
        val = fmaxf(acc, 0.f) + log1pf(expf(-fabsf(acc)));  // softplus (stable)
    } else {
        float m = acc;                               // softmax over warp 2 (threads 64..95)
        for (int o = 16; o; o >>= 1) m = fmaxf(m, __shfl_xor_sync(0xffffffffu, m, o));
        float ex = expf(acc - m);
        float s = ex;
        for (int o = 16; o; o >>= 1) s += __shfl_xor_sync(0xffffffffu, s, o);
        val = ex / s;
    }
    g_xs1[(size_t)row * GMMx + tid] = val;
    int b = row / Nx, n = row - b * Nx;
    pred_out[(((size_t)b * Tx + t) * Nx + n) * GMMx + tid] = val;
}

// z = [x_s, xs1, h] @ W_in + b_in
__global__ void k_zin(const float* __restrict__ x, const float* __restrict__ Wi,
                      const float* __restrict__ bi, int t) {
    int row = blockIdx.x;
    int tid = threadIdx.x;           // 0..63
    __shared__ float sh[RINx];
    int b = row / Nx, n = row - b * Nx;
    for (int i = tid; i < RINx; i += 64) {
        float v;
        if (i == 0)            v = x[((size_t)b * Tx + t) * Nx + n];
        else if (i < 1 + GMMx) v = g_xs1[(size_t)row * GMMx + (i - 1)];
        else                   v = g_h[(size_t)row * Hx + (i - 1 - GMMx)];
        sh[i] = v;
    }
    __syncthreads();
    float acc = bi[tid];
    #pragma unroll 7
    for (int k = 0; k < RINx; k++) acc = fmaf(sh[k], Wi[k * Hx + tid], acc);
    g_z[(size_t)row * Hx + tid] = acc;
}

// gather aggregation: out[b,d,:] = sum_e w_e * src[b, s_e, :]
// mode 0: z(64)->az ; 1: [x2(161),h(64)]->a1 ; 2: a1(225)->a2 ; 3: [x2(161),rh(64)]->a1
__global__ void k_agg(int mode) {
    const float* pa; const float* pb; int dimA, dimB; float* out;
    if      (mode == 0) { pa = g_z;  dimA = Hx;   pb = g_z;  dimB = 0;  out = g_az; }
    else if (mode == 1) { pa = g_x2; dimA = RINx; pb = g_h;  dimB = Hx; out = g_a1; }
    else if (mode == 2) { pa = g_a1; dimA = GINx; pb = g_a1; dimB = 0;  out = g_a2; }
    else                { pa = g_x2; dimA = RINx; pb = g_rh; dimB = Hx; out = g_a1; }
    int dim = dimA + dimB;
    int blk = blockIdx.x;
    int b = blk / Nx, d = blk - b * Nx;
    int tid = threadIdx.x;
    int s0 = g_off[d], s1 = g_off[d + 1];
    __shared__ int   ss[64];
    __shared__ float sw[64];
    float acc = 0.f;
    const float* Pa = pa + (size_t)b * Nx * dimA;
    const float* Pb = pb + (size_t)b * Nx * dimB;
    for (int base = s0; base < s1; base += 64) {
        int m = min(64, s1 - base);
        __syncthreads();
        if (tid < m) { ss[tid] = g_srcs[base + tid]; sw[tid] = g_ws[base + tid]; }
        __syncthreads();
        if (tid < dim) {
            for (int i = 0; i < m; i++) {
                int s = ss[i];
                float v = (tid < dimA) ? Pa[(size_t)s * dimA + tid]
                                       : Pb[(size_t)s * dimB + (tid - dimA)];
                acc = fmaf(sw[i], v, acc);
            }
        }
    }
    if (tid < dim) out[(size_t)blk * dim + tid] = acc;
}

// conv = [z,az] @ W_sd + b ; repr = relu([conv, h]) -> g_repr, representations slice
__global__ void k_sd(const float* __restrict__ Wsd, const float* __restrict__ bsd,
                     float* __restrict__ reps_out, int t) {
    int row = blockIdx.x;
    int tid = threadIdx.x;           // 0..127
    __shared__ float sh[2 * Hx];
    sh[tid] = (tid < Hx) ? g_z[(size_t)row * Hx + tid]
                         : g_az[(size_t)row * Hx + tid - Hx];
    __syncthreads();
    float v;
    if (tid < Hx) {
        float acc = bsd[tid];
        #pragma unroll 8
        for (int k = 0; k < 2 * Hx; k++) acc = fmaf(sh[k], Wsd[k * Hx + tid], acc);
        v = fmaxf(acc, 0.f);
    } else {
        v = fmaxf(g_h[(size_t)row * Hx + tid - Hx], 0.f);
    }
    g_repr[(size_t)row * 2 * Hx + tid] = v;
    int b = row / Nx, n = row - b * Nx;
    reps_out[(((size_t)b * Tx + t) * Nx + n) * (2 * Hx) + tid] = v;
}

// x2 = repr @ W_out + b_out -> g_x2, generations slice
__global__ void k_out(const float* __restrict__ Wout, const float* __restrict__ bout,
                      float* __restrict__ gen_out, int t) {
    int row = blockIdx.x;
    int tid = threadIdx.x;           // 0..191 (161 active)
    __shared__ float sh[2 * Hx];
    if (tid < 2 * Hx) sh[tid] = g_repr[(size_t)row * 2 * Hx + tid];
    __syncthreads();
    if (tid < RINx) {
        float acc = bout[tid];
        #pragma unroll 8
        for (int k = 0; k < 2 * Hx; k++) acc = fmaf(sh[k], Wout[k * RINx + tid], acc);
        g_x2[(size_t)row * RINx + tid] = acc;
        int b = row / Nx, n = row - b * Nx;
        gen_out[(((size_t)b * Tx + t) * Nx + n) * RINx + tid] = acc;
    }
}

// r = sigmoid([xh,a1,a2]@W_r+b_r), g = sigmoid(...W_u...); store rh = r*h, gg = g
__global__ void k_ru(const float* __restrict__ Wr, const float* __restrict__ br,
                     const float* __restrict__ Wu, const float* __restrict__ bu) {
    int row = blockIdx.x;
    int tid = threadIdx.x;           // 0..127
    __shared__ float sh[D3x];
    for (int i = tid; i < D3x; i += 128) {
        float v;
        if      (i < RINx)       v = g_x2[(size_t)row * RINx + i];
        else if (i < GINx)       v = g_h [(size_t)row * Hx + (i - RINx)];
        else if (i < 2 * GINx)   v = g_a1[(size_t)row * GINx + (i - GINx)];
        else                     v = g_a2[(size_t)row * GINx + (i - 2 * GINx)];
        sh[i] = v;
    }
    __syncthreads();
    int j = tid & 63;
    const float* Wp = (tid < 64) ? Wr : Wu;
    float acc = (tid < 64) ? br[j] : bu[j];
    #pragma unroll 9
    for (int k = 0; k < D3x; k++) acc = fmaf(sh[k], Wp[k * Hx + j], acc);
    float sg = 1.f / (1.f + expf(-acc));
    if (tid < 64) g_rh[(size_t)row * Hx + j] = sg * sh[RINx + j];  // r * h
    else          g_gg[(size_t)row * Hx + j] = sg;
}

// c = tanh([cc,b1,b2]@W_c+b_c); h = g*h + (1-g)*c -> states slice
__global__ void k_c(const float* __restrict__ Wc, const float* __restrict__ bc,
                    float* __restrict__ st_out, int t) {
    int row = blockIdx.x;
    int tid = threadIdx.x;           // 0..63
    __shared__ float sh[D3x];
    for (int i = tid; i < D3x; i += 64) {
        float v;
        if      (i < RINx)       v = g_x2[(size_t)row * RINx + i];
        else if (i < GINx)       v = g_rh[(size_t)row * Hx + (i - RINx)];
        else if (i < 2 * GINx)   v = g_a1[(size_t)row * GINx + (i - GINx)];
        else                     v = g_a2[(size_t)row * GINx + (i - 2 * GINx)];
        sh[i] = v;
    }
    __syncthreads();
    float acc = bc[tid];
    #pragma unroll 9
    for (int k = 0; k < D3x; k++) acc = fmaf(sh[k], Wc[k * Hx + tid], acc);
    float c = tanhf(acc);
    float gg = g_gg[(size_t)row * Hx + tid];
    float h  = g_h [(size_t)row * Hx + tid];
    float hn = gg * h + (1.f - gg) * c;
    g_h[(size_t)row * Hx + tid] = hn;
    int b = row / Nx, n = row - b * Nx;
    st_out[(((size_t)b * Tx + t) * Nx + n) * Hx + tid] = hn;
}

// ---------------- launch ----------------
extern "C" void kernel_launch(void* const* d_in, const int* in_sizes, int n_in,
                              void* d_out, int out_size) {
    const float* x    = (const float*)d_in[0];
    const int*   ei   = (const int*)  d_in[1];
    const float* ew   = (const float*)d_in[2];
    const float* Wg   = (const float*)d_in[3];
    const float* bg   = (const float*)d_in[4];
    const float* Wi   = (const float*)d_in[5];
    const float* bi   = (const float*)d_in[6];
    const float* Wsd  = (const float*)d_in[7];
    const float* bsd  = (const float*)d_in[8];
    const float* Wout = (const float*)d_in[9];
    const float* bout = (const float*)d_in[10];
    const float* Wr   = (const float*)d_in[11];
    const float* br   = (const float*)d_in[12];
    const float* Wu   = (const float*)d_in[13];
    const float* bu   = (const float*)d_in[14];
    const float* Wc   = (const float*)d_in[15];
    const float* bc   = (const float*)d_in[16];

    float* out  = (float*)d_out;
    float* gen  = out;
    float* pred = out + (size_t)Bx * Tx * Nx * RINx;
    float* reps = pred + (size_t)Bx * Tx * Nx * GMMx;
    float* st   = reps + (size_t)Bx * Tx * Nx * (2 * Hx);

    // preprocessing (CSR by dst, deterministic)
    k_init   <<<(BNx * Hx + 255) / 256, 256>>>();
    k_count  <<<(Ex + 255) / 256, 256>>>(ei);
    k_scan   <<<1, 32>>>();
    k_scatter<<<(Ex + 255) / 256, 256>>>(ei);
    k_sortfill<<<(Nx + 127) / 128, 128>>>(ei, ew);

    for (int t = 0; t < Tx; t++) {
        k_gmm<<<BNx, 96>>>(Wg, bg, pred, t);
        k_zin<<<BNx, 64>>>(x, Wi, bi, t);
        k_agg<<<BNx, 64>>>(0);                    // az = A z
        k_sd <<<BNx, 128>>>(Wsd, bsd, reps, t);
        k_out<<<BNx, 192>>>(Wout, bout, gen, t);
        k_agg<<<BNx, 256>>>(1);                   // a1 = A xh
        k_agg<<<BNx, 256>>>(2);                   // a2 = A a1
        k_ru <<<BNx, 128>>>(Wr, br, Wu, bu);
        k_agg<<<BNx, 256>>>(3);                   // a1 = A cc
        k_agg<<<BNx, 256>>>(2);                   // a2 = A a1
        k_c  <<<BNx, 64>>>(Wc, bc, st, t);
    }
}

// round 4
// speedup vs baseline: 1.5804x; 1.5804x over previous
#include <cuda_runtime.h>
#include <math.h>

#define Bx   4
#define Tx   12
#define Nx   3000
#define Hx   64
#define Mx   32
#define Ex   96000
#define GMMx 96
#define RINx 161
#define GINx 225
#define D3x  675
#define BNx  (Bx*Nx)
#define Rr   8            // rows per GEMM block
#define NBLK (BNx/Rr)     // 1500

// 8-row FMA core: acc[0..7] plain local array, compile-time indices only.
#define DOT8(Kdim, Wptr, ldw)                                           \
    do {                                                                \
        _Pragma("unroll 4")                                             \
        for (int k = 0; k < (Kdim); k++) {                              \
            float w = __ldg((Wptr) + (size_t)k * (ldw));                \
            float4 v0 = *(const float4*)(sh + k * Rr);                  \
            float4 v1 = *(const float4*)(sh + k * Rr + 4);              \
            acc[0] = fmaf(w, v0.x, acc[0]);                             \
            acc[1] = fmaf(w, v0.y, acc[1]);                             \
            acc[2] = fmaf(w, v0.z, acc[2]);                             \
            acc[3] = fmaf(w, v0.w, acc[3]);                             \
            acc[4] = fmaf(w, v1.x, acc[4]);                             \
            acc[5] = fmaf(w, v1.y, acc[5]);                             \
            acc[6] = fmaf(w, v1.z, acc[6]);                             \
            acc[7] = fmaf(w, v1.w, acc[7]);                             \
        }                                                               \
    } while (0)

// ---------------- device scratch ----------------
__device__ int   g_cnt[Nx];
__device__ int   g_cur[Nx];
__device__ int   g_off[Nx + 1];
__device__ int   g_eid[Ex];
__device__ int   g_srcs[Ex];
__device__ float g_ws[Ex];

__device__ float g_h   [BNx * Hx];
__device__ float g_xs1 [BNx * GMMx];
__device__ float g_z   [BNx * Hx];
__device__ float g_az  [BNx * Hx];
__device__ float g_Ah  [BNx * Hx];
__device__ float g_AAh [BNx * Hx];
__device__ float g_repr[BNx * 2 * Hx];
__device__ float g_x2  [BNx * RINx];
__device__ float g_Ax2 [BNx * RINx];
__device__ float g_AAx2[BNx * RINx];
__device__ float g_rh  [BNx * Hx];
__device__ float g_Arh [BNx * Hx];
__device__ float g_AArh[BNx * Hx];
__device__ float g_gg  [BNx * Hx];

// ---------------- preprocessing: CSR by dst, deterministic ----------------
__global__ void k_init() {
    int i = blockIdx.x * blockDim.x + threadIdx.x;
    if (i < Nx) { g_cnt[i] = 0; g_cur[i] = 0; }
    if (i < BNx * Hx) g_h[i] = 0.f;
}
__global__ void k_count(const int* __restrict__ ei) {
    int e = blockIdx.x * blockDim.x + threadIdx.x;
    if (e < Ex) atomicAdd(&g_cnt[ei[Ex + e]], 1);
}
__global__ void k_scan() {
    int lane = threadIdx.x;
    const int CH = (Nx + 31) / 32;
    int st = lane * CH, en = min(Nx, st + CH);
    int s = 0;
    for (int i = st; i < en; i++) s += g_cnt[i];
    int acc = s;
    for (int o = 1; o < 32; o <<= 1) {
        int v = __shfl_up_sync(0xffffffffu, acc, o);
        if (lane >= o) acc += v;
    }
    int base = acc - s;
    for (int i = st; i < en; i++) { g_off[i] = base; base += g_cnt[i]; }
    if (lane == 31) g_off[Nx] = base;
}
__global__ void k_scatter(const int* __restrict__ ei) {
    int e = blockIdx.x * blockDim.x + threadIdx.x;
    if (e < Ex) {
        int d = ei[Ex + e];
        int p = atomicAdd(&g_cur[d], 1);
        g_eid[g_off[d] + p] = e;
    }
}
__global__ void k_sortfill(const int* __restrict__ ei, const float* __restrict__ ew) {
    int d = blockIdx.x * blockDim.x + threadIdx.x;
    if (d >= Nx) return;
    int s = g_off[d], t = g_off[d + 1];
    for (int i = s + 1; i < t; i++) {
        int v = g_eid[i];
        int j = i - 1;
        while (j >= s && g_eid[j] > v) { g_eid[j + 1] = g_eid[j]; j--; }
        g_eid[j + 1] = v;
    }
    for (int i = s; i < t; i++) {
        int e = g_eid[i];
        g_srcs[i] = ei[e];
        g_ws[i]   = ew[e];
    }
}

// ---------------- step kernels ----------------
// raw = h @ W_gmm + b; mu | softplus | softmax -> g_xs1, predictions
__global__ void k_gmm(const float* __restrict__ Wg, const float* __restrict__ bg,
                      float* __restrict__ pred_out, int t) {
    __shared__ __align__(16) float sh[Hx * Rr];
    int tid = threadIdx.x;               // 0..95
    int row0 = blockIdx.x * Rr;
    for (int idx = tid; idx < Hx * Rr; idx += 96) {
        int r = idx & (Rr - 1), k = idx >> 3;
        sh[idx] = g_h[(size_t)(row0 + r) * Hx + k];
    }
    __syncthreads();
    float acc[Rr];
    float b0 = bg[tid];
    #pragma unroll
    for (int r = 0; r < Rr; r++) acc[r] = b0;
    DOT8(Hx, Wg + tid, GMMx);
    #pragma unroll
    for (int r = 0; r < Rr; r++) {
        float a = acc[r], val;
        if (tid < Mx) {
            val = a;
        } else if (tid < 2 * Mx) {
            val = fmaxf(a, 0.f) + log1pf(expf(-fabsf(a)));
        } else {
            float m = a;
            for (int o = 16; o; o >>= 1) m = fmaxf(m, __shfl_xor_sync(0xffffffffu, m, o));
            float ex = expf(a - m);
            float s = ex;
            for (int o = 16; o; o >>= 1) s += __shfl_xor_sync(0xffffffffu, s, o);
            val = ex / s;
        }
        int row = row0 + r;
        g_xs1[(size_t)row * GMMx + tid] = val;
        int b = row / Nx, n = row - b * Nx;
        pred_out[(((size_t)b * Tx + t) * Nx + n) * GMMx + tid] = val;
    }
}

// z = [x_s, xs1, h] @ W_in + b_in
__global__ void k_zin(const float* __restrict__ x, const float* __restrict__ Wi,
                      const float* __restrict__ bi, int t) {
    __shared__ __align__(16) float sh[RINx * Rr];
    int tid = threadIdx.x;               // 0..63
    int row0 = blockIdx.x * Rr;
    for (int idx = tid; idx < RINx * Rr; idx += 64) {
        int r = idx & (Rr - 1), k = idx >> 3;
        int row = row0 + r;
        float v;
        if (k == 0) {
            int b = row / Nx, n = row - b * Nx;
            v = x[((size_t)b * Tx + t) * Nx + n];
        } else if (k < 1 + GMMx) v = g_xs1[(size_t)row * GMMx + (k - 1)];
        else                     v = g_h[(size_t)row * Hx + (k - 1 - GMMx)];
        sh[idx] = v;
    }
    __syncthreads();
    float acc[Rr];
    float b0 = bi[tid];
    #pragma unroll
    for (int r = 0; r < Rr; r++) acc[r] = b0;
    DOT8(RINx, Wi + tid, Hx);
    #pragma unroll
    for (int r = 0; r < Rr; r++) g_z[(size_t)(row0 + r) * Hx + tid] = acc[r];
}

// gather aggregation, two output segments, all pointers resolved DEVICE-side
// mode 0: az=Az(64), Ah=Ah(64)   128 thr
// mode 1: Ax2=A x2(161)          192 thr
// mode 2: AAx2=A Ax2(161), AAh=A Ah(64)  256 thr
// mode 3: Arh=A rh(64)           64 thr
// mode 4: AArh=A Arh(64)         64 thr
__global__ void k_agg(int mode) {
    const float* A; const float* Bp = 0; float* OA; float* OB = 0;
    int dA, dB = 0;
    switch (mode) {
        case 0:  A = g_z;   dA = Hx;   OA = g_az;   Bp = g_h;  dB = Hx; OB = g_Ah;  break;
        case 1:  A = g_x2;  dA = RINx; OA = g_Ax2;                                  break;
        case 2:  A = g_Ax2; dA = RINx; OA = g_AAx2; Bp = g_Ah; dB = Hx; OB = g_AAh; break;
        case 3:  A = g_rh;  dA = Hx;   OA = g_Arh;                                  break;
        default: A = g_Arh; dA = Hx;   OA = g_AArh;                                 break;
    }
    int blk = blockIdx.x;
    int b = blk / Nx, d = blk - b * Nx;
    int tid = threadIdx.x;
    int s0 = g_off[d], s1 = g_off[d + 1];
    __shared__ int   ss[64];
    __shared__ float sw[64];
    bool inA = tid < dA;
    bool active = tid < dA + dB;
    int dim = inA ? dA : dB;
    int c   = inA ? tid : tid - dA;
    const float* P = inA ? (A + (size_t)b * Nx * dA) : (Bp + (size_t)b * Nx * dB);
    float acc = 0.f;
    for (int base = s0; base < s1; base += 64) {
        int m = min(64, s1 - base);
        __syncthreads();
        if (tid < m) { ss[tid] = g_srcs[base + tid]; sw[tid] = g_ws[base + tid]; }
        __syncthreads();
        if (active) {
            for (int i = 0; i < m; i++)
                acc = fmaf(sw[i], P[(size_t)ss[i] * dim + c], acc);
        }
    }
    if (active) {
        if (inA) OA[(size_t)blk * dA + c] = acc;
        else     OB[(size_t)blk * dB + c] = acc;
    }
}

// conv = [z,az]@W_sd+b; repr = relu([conv,h]) -> g_repr, representations
__global__ void k_sd(const float* __restrict__ Wsd, const float* __restrict__ bsd,
                     float* __restrict__ reps_out, int t) {
    __shared__ __align__(16) float sh[2 * Hx * Rr];
    int tid = threadIdx.x;               // 0..63
    int row0 = blockIdx.x * Rr;
    for (int idx = tid; idx < 2 * Hx * Rr; idx += 64) {
        int r = idx & (Rr - 1), k = idx >> 3;
        int row = row0 + r;
        sh[idx] = (k < Hx) ? g_z[(size_t)row * Hx + k]
                           : g_az[(size_t)row * Hx + (k - Hx)];
    }
    __syncthreads();
    float acc[Rr];
    float b0 = bsd[tid];
    #pragma unroll
    for (int r = 0; r < Rr; r++) acc[r] = b0;
    DOT8(2 * Hx, Wsd + tid, Hx);
    #pragma unroll
    for (int r = 0; r < Rr; r++) {
        int row = row0 + r;
        float v1 = fmaxf(acc[r], 0.f);
        float v2 = fmaxf(g_h[(size_t)row * Hx + tid], 0.f);
        g_repr[(size_t)row * 2 * Hx + tid]      = v1;
        g_repr[(size_t)row * 2 * Hx + Hx + tid] = v2;
        int b = row / Nx, n = row - b * Nx;
        size_t o = (((size_t)b * Tx + t) * Nx + n) * (2 * Hx);
        reps_out[o + tid]      = v1;
        reps_out[o + Hx + tid] = v2;
    }
}

// x2 = repr @ W_out + b_out -> g_x2, generations
__global__ void k_out(const float* __restrict__ Wout, const float* __restrict__ bout,
                      float* __restrict__ gen_out, int t) {
    __shared__ __align__(16) float sh[2 * Hx * Rr];
    int tid = threadIdx.x;               // 0..191 (161 active)
    int row0 = blockIdx.x * Rr;
    for (int idx = tid; idx < 2 * Hx * Rr; idx += 192) {
        int r = idx & (Rr - 1), k = idx >> 3;
        sh[idx] = g_repr[(size_t)(row0 + r) * 2 * Hx + k];
    }
    __syncthreads();
    if (tid >= RINx) return;
    float acc[Rr];
    float b0 = bout[tid];
    #pragma unroll
    for (int r = 0; r < Rr; r++) acc[r] = b0;
    DOT8(2 * Hx, Wout + tid, RINx);
    #pragma unroll
    for (int r = 0; r < Rr; r++) {
        int row = row0 + r;
        g_x2[(size_t)row * RINx + tid] = acc[r];
        int b = row / Nx, n = row - b * Nx;
        gen_out[(((size_t)b * Tx + t) * Nx + n) * RINx + tid] = acc[r];
    }
}

// fetch of the 675-dim concat [x2, P, Ax2, AP, AAx2, AAP]
__device__ __forceinline__ float fetch675(int row, int k,
                                          const float* __restrict__ P,
                                          const float* __restrict__ AP,
                                          const float* __restrict__ AAP) {
    if (k < RINx)            return g_x2  [(size_t)row * RINx + k];
    if (k < GINx)            return P     [(size_t)row * Hx   + (k - RINx)];
    if (k < GINx + RINx)     return g_Ax2 [(size_t)row * RINx + (k - GINx)];
    if (k < 2 * GINx)        return AP    [(size_t)row * Hx   + (k - GINx - RINx)];
    if (k < 2 * GINx + RINx) return g_AAx2[(size_t)row * RINx + (k - 2 * GINx)];
    return AAP[(size_t)row * Hx + (k - 2 * GINx - RINx)];
}

// r,u gates: 128 threads (0..63 -> W_r, 64..127 -> W_u); rh = r*h, gg = g
__global__ void k_ru(const float* __restrict__ Wr, const float* __restrict__ br,
                     const float* __restrict__ Wu, const float* __restrict__ bu) {
    __shared__ __align__(16) float sh[D3x * Rr];
    int tid = threadIdx.x;
    int row0 = blockIdx.x * Rr;
    for (int idx = tid; idx < D3x * Rr; idx += 128) {
        int r = idx & (Rr - 1), k = idx >> 3;
        sh[idx] = fetch675(row0 + r, k, g_h, g_Ah, g_AAh);
    }
    __syncthreads();
    int col = tid & 63;
    const float* Wp = (tid < 64) ? Wr : Wu;
    float acc[Rr];
    float b0 = (tid < 64) ? br[col] : bu[col];
    #pragma unroll
    for (int r = 0; r < Rr; r++) acc[r] = b0;
    DOT8(D3x, Wp + col, Hx);
    #pragma unroll
    for (int r = 0; r < Rr; r++) {
        int row = row0 + r;
        float sg = 1.f / (1.f + expf(-acc[r]));
        if (tid < 64) g_rh[(size_t)row * Hx + col] = sg * g_h[(size_t)row * Hx + col];
        else          g_gg[(size_t)row * Hx + col] = sg;
    }
}

// c = tanh(...); h = g*h + (1-g)*c -> states
__global__ void k_c(const float* __restrict__ Wc, const float* __restrict__ bc,
                    float* __restrict__ st_out, int t) {
    __shared__ __align__(16) float sh[D3x * Rr];
    int tid = threadIdx.x;               // 0..63
    int row0 = blockIdx.x * Rr;
    for (int idx = tid; idx < D3x * Rr; idx += 64) {
        int r = idx & (Rr - 1), k = idx >> 3;
        sh[idx] = fetch675(row0 + r, k, g_rh, g_Arh, g_AArh);
    }
    __syncthreads();
    float acc[Rr];
    float b0 = bc[tid];
    #pragma unroll
    for (int r = 0; r < Rr; r++) acc[r] = b0;
    DOT8(D3x, Wc + tid, Hx);
    #pragma unroll
    for (int r = 0; r < Rr; r++) {
        int row = row0 + r;
        float c = tanhf(acc[r]);
        float gg = g_gg[(size_t)row * Hx + tid];
        float h  = g_h [(size_t)row * Hx + tid];
        float hn = gg * h + (1.f - gg) * c;
        g_h[(size_t)row * Hx + tid] = hn;
        int b = row / Nx, n = row - b * Nx;
        st_out[(((size_t)b * Tx + t) * Nx + n) * Hx + tid] = hn;
    }
}

// ---------------- launch ----------------
extern "C" void kernel_launch(void* const* d_in, const int* in_sizes, int n_in,
                              void* d_out, int out_size) {
    const float* x    = (const float*)d_in[0];
    const int*   ei   = (const int*)  d_in[1];
    const float* ew   = (const float*)d_in[2];
    const float* Wg   = (const float*)d_in[3];
    const float* bg   = (const float*)d_in[4];
    const float* Wi   = (const float*)d_in[5];
    const float* bi   = (const float*)d_in[6];
    const float* Wsd  = (const float*)d_in[7];
    const float* bsd  = (const float*)d_in[8];
    const float* Wout = (const float*)d_in[9];
    const float* bout = (const float*)d_in[10];
    const float* Wr   = (const float*)d_in[11];
    const float* br   = (const float*)d_in[12];
    const float* Wu   = (const float*)d_in[13];
    const float* bu   = (const float*)d_in[14];
    const float* Wc   = (const float*)d_in[15];
    const float* bc   = (const float*)d_in[16];

    float* out  = (float*)d_out;
    float* gen  = out;
    float* pred = out + (size_t)Bx * Tx * Nx * RINx;
    float* reps = pred + (size_t)Bx * Tx * Nx * GMMx;
    float* st   = reps + (size_t)Bx * Tx * Nx * (2 * Hx);

    k_init    <<<(BNx * Hx + 255) / 256, 256>>>();
    k_count   <<<(Ex + 255) / 256, 256>>>(ei);
    k_scan    <<<1, 32>>>();
    k_scatter <<<(Ex + 255) / 256, 256>>>(ei);
    k_sortfill<<<(Nx + 127) / 128, 128>>>(ei, ew);

    for (int t = 0; t < Tx; t++) {
        k_gmm<<<NBLK, 96>>>(Wg, bg, pred, t);
        k_zin<<<NBLK, 64>>>(x, Wi, bi, t);
        k_agg<<<BNx, 128>>>(0);                 // az, Ah
        k_sd <<<NBLK, 64>>>(Wsd, bsd, reps, t);
        k_out<<<NBLK, 192>>>(Wout, bout, gen, t);
        k_agg<<<BNx, 192>>>(1);                 // Ax2
        k_agg<<<BNx, 256>>>(2);                 // AAx2, AAh
        k_ru <<<NBLK, 128>>>(Wr, br, Wu, bu);
        k_agg<<<BNx, 64>>>(3);                  // Arh
        k_agg<<<BNx, 64>>>(4);                  // AArh
        k_c  <<<NBLK, 64>>>(Wc, bc, st, t);
    }
}